// round 10
// baseline (speedup 1.0000x reference)
#include <cuda_runtime.h>

// ---------------------------------------------------------------------------
// N=262144 rows, three streams x[N,80]. R_a = BN(x W_a^T + b_a) (batch stats).
// sims = rowwise dots of R pairs -> softmax over 3 -> blend of inputs.
//
// Closed forms:
//   mu_j  = w_j.xbar + b_j
//   var_j = w_j^T (X^T X / N) w_j - (w_j.xbar)^2
//   sim_ab(i) = x_a^T M_ab x_b + u_ab.x_a + v_ab.x_b + c_ab,  M_ab = Wh_a^T Wh_b
//
// R10: 4 launches (xtx, reduceC, prep, main) — no atomics, no zero kernel.
// ---------------------------------------------------------------------------

#define DIN    80
#define DOUT   160
#define NROWS  262144
#define EPSV   1e-5f

#define P1_BLOCKS  256        // blocks per stream (pass 1)
#define P1_TILES   8          // 128-row tiles per block: 256*8*128 = 262144
#define P1_THREADS 128

#define BR 64                 // rows per block (pass 2)
#define XP 68                 // transposed-x smem pitch (floats)

// ---- device scratch (static: no runtime allocation allowed) ---------------
__device__ float gSpart[3 * P1_BLOCKS * DIN];            // per-block col sums
__device__ float gS[3 * DIN];                            // column sums
__device__ float gCpart[(size_t)3 * P1_BLOCKS * DIN*DIN];// per-block XtX partials
__device__ float gC[3 * DIN * DIN];                      // XtX per stream
__device__ float gM[3 * DIN * DIN];                      // bilinear matrices
__device__ float gU[3 * DIN];
__device__ float gV[3 * DIN];
__device__ float gCc[3];

struct Params {
    const float* W[3];
    const float* b[3];
    const float* g[3];
    const float* be[3];
};

// packed dual FMA (fma-pipe 2x vs scalar FFMA; PTX-only on sm_10x)
__device__ __forceinline__ float2 ffma2(float2 a, float2 b, float2 c) {
    float2 d;
    asm("fma.rn.f32x2 %0, %1, %2, %3;"
        : "=l"(reinterpret_cast<unsigned long long&>(d))
        : "l"(reinterpret_cast<unsigned long long&>(a)),
          "l"(reinterpret_cast<unsigned long long&>(b)),
          "l"(reinterpret_cast<unsigned long long&>(c)));
    return d;
}

// ---------------------------------------------------------------------------
// K1: per-block partial X^T X (upper block-triangle only) + column-sum
// partials. 128 threads = 8(tj) x 16(tk); 5 j-pairs x 5 k float2 tiles.
// All outputs are pure stores (graph-replay safe without zeroing).
// ---------------------------------------------------------------------------
__global__ __launch_bounds__(P1_THREADS)
void k_xtx(const float* __restrict__ X0, const float* __restrict__ X1,
           const float* __restrict__ X2)
{
    __shared__ __align__(16) float Xs[128 * DIN];

    const int s = blockIdx.y;
    const float* X = (s == 0) ? X0 : (s == 1) ? X1 : X2;
    const int tid = threadIdx.x;
    const int tj = tid & 7;       // 0..7
    const int tk = tid >> 3;      // 0..15

    float2 acc[5][5];
#pragma unroll
    for (int a = 0; a < 5; ++a)
#pragma unroll
        for (int b = 0; b < 5; ++b) acc[a][b] = make_float2(0.f, 0.f);
    float csum = 0.f;

    const long long rowbase = (long long)blockIdx.x * (P1_TILES * 128);

    for (int t = 0; t < P1_TILES; ++t) {
        const float4* src4 =
            (const float4*)(X + (rowbase + (long long)t * 128) * DIN);
        float4* Xs4 = (float4*)Xs;
#pragma unroll
        for (int i = 0; i < (128 * DIN / 4) / P1_THREADS; ++i)
            Xs4[tid + i * P1_THREADS] = src4[tid + i * P1_THREADS];
        __syncthreads();

#pragma unroll 2
        for (int r = 0; r < 128; ++r) {
            const float* row = &Xs[r * DIN];
            float2 xj[5];
            float  xk[5];
#pragma unroll
            for (int a = 0; a < 5; ++a)
                xj[a] = *(const float2*)&row[2 * (tj + 8 * a)];
#pragma unroll
            for (int b = 0; b < 5; ++b)
                xk[b] = row[tk + 16 * b];
#pragma unroll
            for (int a = 0; a < 5; ++a)
#pragma unroll
                for (int b = a; b < 5; ++b) {
                    float2 kk = make_float2(xk[b], xk[b]);
                    acc[a][b] = ffma2(xj[a], kk, acc[a][b]);
                }
        }

        if (tid < DIN) {
            float ss = 0.f;
#pragma unroll 8
            for (int r = 0; r < 128; ++r) ss += Xs[r * DIN + tid];
            csum += ss;
        }
        __syncthreads();
    }

    float* dst = gCpart + (size_t)(s * P1_BLOCKS + blockIdx.x) * (DIN * DIN);
#pragma unroll
    for (int a = 0; a < 5; ++a)
#pragma unroll
        for (int b = a; b < 5; ++b) {
            int j0 = 2 * (tj + 8 * a);
            int k  = tk + 16 * b;
            dst[j0 * DIN + k]       = acc[a][b].x;
            dst[(j0 + 1) * DIN + k] = acc[a][b].y;
        }
    if (tid < DIN)
        gSpart[(s * P1_BLOCKS + blockIdx.x) * DIN + tid] = csum;
}

// ---------------------------------------------------------------------------
// K2: reduce partials -> gC (mirror lower triangle) and gSpart -> gS.
// ---------------------------------------------------------------------------
__global__ void k_reduceC()
{
    int e = blockIdx.x * blockDim.x + threadIdx.x;
    if (e < 3 * DIN * DIN) {
        int s   = e / (DIN * DIN);
        int rem = e - s * DIN * DIN;
        int j = rem / DIN, k = rem - j * DIN;
        int jt = j >> 4, kt = k >> 4;
        if (jt > kt || (jt == kt && j > k)) return;   // mirror handles these

        const float* src = gCpart + (size_t)s * P1_BLOCKS * (DIN * DIN) + rem;
        float acc = 0.f;
#pragma unroll 8
        for (int b = 0; b < P1_BLOCKS; ++b)
            acc += src[(size_t)b * (DIN * DIN)];
        gC[s * DIN * DIN + j * DIN + k] = acc;
        gC[s * DIN * DIN + k * DIN + j] = acc;
    } else if (e < 3 * DIN * DIN + 3 * DIN) {
        int h = e - 3 * DIN * DIN;
        int s = h / DIN, k = h - s * DIN;
        float acc = 0.f;
#pragma unroll 8
        for (int b = 0; b < P1_BLOCKS; ++b)
            acc += gSpart[(s * P1_BLOCKS + b) * DIN + k];
        gS[s * DIN + k] = acc;
    }
}

// ---------------------------------------------------------------------------
// K3 (fused stats + buildM): grid = 3 blocks (one per pair), 256 threads.
// Per stream of the pair: T = W*C tiled GEMM -> diag partials -> alpha, d
// -> Wh = alpha*W in place (smem). Then M = WhA^T WhB tiled GEMM, u, v, c.
// ---------------------------------------------------------------------------
#define WP 84                                   // W smem pitch (16B-friendly)
#define TPP (DOUT + 8)                          // Tpart pitch
#define PREP_FLOATS (2*DOUT*WP + DIN*DIN + 16*TPP + DOUT + DIN + 2*DOUT)
#define PREP_SMEM (PREP_FLOATS * 4)             // ~146 KB

__global__ __launch_bounds__(256)
void k_prep(Params P, float invN)
{
    extern __shared__ __align__(16) float sp[];
    float* WsA    = sp;                         // [160][WP]
    float* WsB    = WsA + DOUT * WP;            // [160][WP]
    float* Cs     = WsB + DOUT * WP;            // [80][80]
    float* Tp     = Cs + DIN * DIN;             // [16][TPP]
    float* alphas = Tp + 16 * TPP;              // [160]
    float* xbs    = alphas + DOUT;              // [80]
    float* dA     = xbs + DIN;                  // [160]
    float* dB     = dA + DOUT;                  // [160]

    const int s = blockIdx.x;
    const int a_idx = (s == 2) ? 1 : 0;         // pa = {0,0,1}
    const int b_idx = (s == 0) ? 1 : 2;         // pb = {1,2,2}
    const int tid = threadIdx.x;
    const int tj = tid & 15, tk = tid >> 4;

    for (int ph = 0; ph < 2; ++ph) {
        const int t  = ph ? b_idx : a_idx;
        float* Ws    = ph ? WsB : WsA;
        float* dd    = ph ? dB : dA;

        // load W [160][80] (float4 rows into pitch-84 smem), C, xbar
        const float4* Wg4 = (const float4*)P.W[t];
        for (int i4 = tid; i4 < DOUT * 20; i4 += 256) {
            int j = i4 / 20, k4 = i4 - j * 20;
            *(float4*)&Ws[j * WP + 4 * k4] = Wg4[i4];
        }
        const float4* Cg4 = (const float4*)&gC[t * DIN * DIN];
        float4* Cs4 = (float4*)Cs;
        for (int i4 = tid; i4 < (DIN * DIN) / 4; i4 += 256) Cs4[i4] = Cg4[i4];
        if (tid < DIN) xbs[tid] = gS[t * DIN + tid] * invN;
        __syncthreads();

        // T = W*C, per-thread tile 10(j) x 5(p); fold into diag partials
        float acc[10][5];
#pragma unroll
        for (int aa = 0; aa < 10; ++aa)
#pragma unroll
            for (int bb = 0; bb < 5; ++bb) acc[aa][bb] = 0.f;

        for (int m = 0; m < DIN; ++m) {
            float wv[10], cv[5];
#pragma unroll
            for (int aa = 0; aa < 10; ++aa) wv[aa] = Ws[(tj + 16 * aa) * WP + m];
#pragma unroll
            for (int bb = 0; bb < 5; ++bb)  cv[bb] = Cs[m * DIN + tk + 16 * bb];
#pragma unroll
            for (int aa = 0; aa < 10; ++aa)
#pragma unroll
                for (int bb = 0; bb < 5; ++bb)
                    acc[aa][bb] += wv[aa] * cv[bb];
        }
#pragma unroll
        for (int aa = 0; aa < 10; ++aa) {
            float psum = 0.f;
#pragma unroll
            for (int bb = 0; bb < 5; ++bb)
                psum += acc[aa][bb] * Ws[(tj + 16 * aa) * WP + tk + 16 * bb];
            Tp[tk * TPP + tj + 16 * aa] = psum;
        }
        __syncthreads();

        if (tid < DOUT) {
            float q = 0.f;
#pragma unroll
            for (int g = 0; g < 16; ++g) q += Tp[g * TPP + tid];
            float wx = 0.f;
#pragma unroll 8
            for (int m = 0; m < DIN; ++m) wx += Ws[tid * WP + m] * xbs[m];
            float bj    = P.b[t][tid];
            float mu    = wx + bj;
            float var   = q * invN - wx * wx;
            float alpha = P.g[t][tid] * rsqrtf(var + EPSV);
            dd[tid]     = alpha * bj + (P.be[t][tid] - mu * alpha);
            alphas[tid] = alpha;
        }
        __syncthreads();

        for (int i = tid; i < DOUT * DIN; i += 256) {
            int j = i / DIN, m = i - j * DIN;
            Ws[j * WP + m] *= alphas[j];
        }
        __syncthreads();
    }

    // M = WhA^T WhB: out 80x80, per-thread 5(p) x 5(q)
    float macc[5][5];
#pragma unroll
    for (int aa = 0; aa < 5; ++aa)
#pragma unroll
        for (int bb = 0; bb < 5; ++bb) macc[aa][bb] = 0.f;

    for (int j = 0; j < DOUT; ++j) {
        float av[5], bv[5];
#pragma unroll
        for (int aa = 0; aa < 5; ++aa) av[aa] = WsA[j * WP + tj + 16 * aa];
#pragma unroll
        for (int bb = 0; bb < 5; ++bb) bv[bb] = WsB[j * WP + tk + 16 * bb];
#pragma unroll
        for (int aa = 0; aa < 5; ++aa)
#pragma unroll
            for (int bb = 0; bb < 5; ++bb)
                macc[aa][bb] += av[aa] * bv[bb];
    }
#pragma unroll
    for (int aa = 0; aa < 5; ++aa)
#pragma unroll
        for (int bb = 0; bb < 5; ++bb)
            gM[s * DIN * DIN + (tj + 16 * aa) * DIN + (tk + 16 * bb)] =
                macc[aa][bb];

    // u[p] = sum_j WhA[j][p] dB[j];  v[q] = sum_j dA[j] WhB[j][q];  c = dA.dB
    if (tid < DIN) {
        float u = 0.f;
        for (int j = 0; j < DOUT; ++j) u += WsA[j * WP + tid] * dB[j];
        gU[s * DIN + tid] = u;
    } else if (tid < 2 * DIN) {
        int q = tid - DIN;
        float v = 0.f;
        for (int j = 0; j < DOUT; ++j) v += dA[j] * WsB[j * WP + q];
        gV[s * DIN + q] = v;
    } else if (tid == 2 * DIN) {
        float c = 0.f;
        for (int j = 0; j < DOUT; ++j) c += dA[j] * dB[j];
        gCc[s] = c;
    }
}

// ---------------------------------------------------------------------------
// K4: main pass. 64 rows/block, 256 threads = 16(tr: 4 rows) x 16(tc: 5 p).
// Per pair: Z = M x_b via 4x5 float2 register tiles (q-pair packed),
// epilogue folds u, dots with x_a -> psum[16][XP] -> gather (no atomics).
// Then v-dots, softmax, blend, float4 store. ~98 KB smem -> 2 blocks/SM.
// ---------------------------------------------------------------------------
#define SM_XT   0
#define SM_M    (3 * DIN * XP)            // 16320
#define SM_U    (SM_M + DIN * DIN)        // 22720
#define SM_V    (SM_U + DIN)              // 22800
#define SM_SIM  (SM_V + 3 * DIN)          // 23040
#define SM_P    (SM_SIM + 3 * BR)         // 23232
#define SM_CC   (SM_P + 3 * BR)           // 23424
#define SM_PS   (SM_CC + 4)               // 23428
#define SM_TOT  (SM_PS + 16 * XP)         // 24516 floats
#define SMEM_BYTES (SM_TOT * 4)           // 98064 B

__global__ __launch_bounds__(256, 2)
void k_main(const float* __restrict__ X0, const float* __restrict__ X1,
            const float* __restrict__ X2, float* __restrict__ out)
{
    extern __shared__ __align__(16) float sm[];
    float* XT   = sm + SM_XT;     // [3][80][XP], element (s, q, r)
    float* Msm  = sm + SM_M;      // [80][80]
    float* usm  = sm + SM_U;      // [80]
    float* vsm  = sm + SM_V;      // [3][80]
    float* sims = sm + SM_SIM;    // [3][64]
    float* psm  = sm + SM_P;      // [3][64]
    float* ccs  = sm + SM_CC;     // [3]
    float* psum = sm + SM_PS;     // [16][XP]

    const int tid = threadIdx.x;
    const int tr  = tid & 15;     // rows 4*tr .. 4*tr+3
    const int tc  = tid >> 4;     // p = tc + 16*c
    const long long base = (long long)blockIdx.x * BR;

    // ---- phase A: load (float4) + transpose x tiles; load v, c ------------
    const float* Xp[3] = {X0, X1, X2};
    for (int s = 0; s < 3; ++s) {
        const float4* src4 = (const float4*)(Xp[s] + base * DIN);
        float* dst = XT + s * DIN * XP;
        for (int i4 = tid; i4 < BR * DIN / 4; i4 += 256) {
            int r  = i4 / 20;
            int k4 = i4 - r * 20;
            float4 v = src4[i4];
            dst[(4 * k4 + 0) * XP + r] = v.x;
            dst[(4 * k4 + 1) * XP + r] = v.y;
            dst[(4 * k4 + 2) * XP + r] = v.z;
            dst[(4 * k4 + 3) * XP + r] = v.w;
        }
    }
    if (tid < 3 * DIN) vsm[tid] = gV[tid];
    if (tid < 3)       ccs[tid] = gCc[tid];
    __syncthreads();

    for (int s = 0; s < 3; ++s) {
        // pa = {0,0,1}, pb = {1,2,2}
        const int a_idx = (s == 2) ? 1 : 0;
        const int b_idx = (s == 0) ? 1 : 2;

        // load M (vectorized), u for this pair (L2-hot)
        const float4* Mg4 = (const float4*)&gM[s * DIN * DIN];
        float4* Ms4 = (float4*)Msm;
        for (int i = tid; i < (DIN * DIN) / 4; i += 256) Ms4[i] = Mg4[i];
        if (tid < DIN) usm[tid] = gU[s * DIN + tid];
        __syncthreads();

        const float* XTb = XT + b_idx * DIN * XP;
        const float* XTa = XT + a_idx * DIN * XP;

        float2 acc[4][5];
#pragma unroll
        for (int r = 0; r < 4; ++r)
#pragma unroll
            for (int c = 0; c < 5; ++c) acc[r][c] = make_float2(0.f, 0.f);

#pragma unroll 4
        for (int qq = 0; qq < DIN / 2; ++qq) {
            float4 e0 = *(const float4*)&XTb[(2 * qq) * XP + 4 * tr];
            float4 o0 = *(const float4*)&XTb[(2 * qq + 1) * XP + 4 * tr];
            float2 xv[4] = {
                {e0.x, o0.x}, {e0.y, o0.y}, {e0.z, o0.z}, {e0.w, o0.w}};
            float2 mv[5];
#pragma unroll
            for (int c = 0; c < 5; ++c)
                mv[c] = *(const float2*)&Msm[(tc + 16 * c) * DIN + 2 * qq];
#pragma unroll
            for (int r = 0; r < 4; ++r)
#pragma unroll
                for (int c = 0; c < 5; ++c)
                    acc[r][c] = ffma2(xv[r], mv[c], acc[r][c]);
        }

        // ---- epilogue: part[r] = sum_c (z + u[p]) * x_a[p][4tr+r] ---------
        float part[4] = {0.f, 0.f, 0.f, 0.f};
#pragma unroll
        for (int c = 0; c < 5; ++c) {
            int p = tc + 16 * c;
            float u = usm[p];
            float4 a0 = *(const float4*)&XTa[p * XP + 4 * tr];
            float av[4] = {a0.x, a0.y, a0.z, a0.w};
#pragma unroll
            for (int r = 0; r < 4; ++r)
                part[r] += (acc[r][c].x + acc[r][c].y + u) * av[r];
        }
#pragma unroll
        for (int r = 0; r < 4; ++r)
            psum[tc * XP + 4 * tr + r] = part[r];
        __syncthreads();

        if (tid < BR) {                 // gather across the 16 tc groups
            float v = 0.f;
#pragma unroll
            for (int t = 0; t < 16; ++t) v += psum[t * XP + tid];
            sims[s * BR + tid] = v;
        }
        __syncthreads();   // gather done before next pair reuses psum/Msm
    }

    // ---- per-row: add v-dots + c, softmax over the 3 sims ------------------
    if (tid < BR) {
        const int r = tid;
        const float* x1 = XT + 1 * DIN * XP;
        const float* x2 = XT + 2 * DIN * XP;
        float d0 = 0.f, d1 = 0.f, d2 = 0.f;
#pragma unroll 8
        for (int q = 0; q < DIN; ++q) {
            float a = x1[q * XP + r];
            float b = x2[q * XP + r];
            d0 += vsm[q] * a;           // pair 01: v . x_left
            d1 += vsm[DIN + q] * b;     // pair 02: v . x_right
            d2 += vsm[2 * DIN + q] * b; // pair 12: v . x_right
        }
        float s0 = sims[0 * BR + r] + d0 + ccs[0];
        float s1 = sims[1 * BR + r] + d1 + ccs[1];
        float s2 = sims[2 * BR + r] + d2 + ccs[2];
        float m  = fmaxf(s0, fmaxf(s1, s2));
        float e0 = __expf(s0 - m), e1 = __expf(s1 - m), e2 = __expf(s2 - m);
        float inv = 1.f / (e0 + e1 + e2);
        psm[0 * BR + r] = e0 * inv;
        psm[1 * BR + r] = e1 * inv;
        psm[2 * BR + r] = e2 * inv;
    }
    __syncthreads();

    // ---- blend + float4 store: out = p0*left + p1*right + p2*sub ----------
    float4* dst4 = (float4*)(out + base * DIN);
    for (int i4 = tid; i4 < BR * DIN / 4; i4 += 256) {
        int r  = i4 / 20;
        int k4 = i4 - r * 20;
        float p0 = psm[r], p1 = psm[BR + r], p2 = psm[2 * BR + r];
        float4 o;
        {
            int k = 4 * k4;
            o.x = p0 * XT[1*DIN*XP + (k+0)*XP + r] + p1 * XT[2*DIN*XP + (k+0)*XP + r] + p2 * XT[(k+0)*XP + r];
            o.y = p0 * XT[1*DIN*XP + (k+1)*XP + r] + p1 * XT[2*DIN*XP + (k+1)*XP + r] + p2 * XT[(k+1)*XP + r];
            o.z = p0 * XT[1*DIN*XP + (k+2)*XP + r] + p1 * XT[2*DIN*XP + (k+2)*XP + r] + p2 * XT[(k+2)*XP + r];
            o.w = p0 * XT[1*DIN*XP + (k+3)*XP + r] + p1 * XT[2*DIN*XP + (k+3)*XP + r] + p2 * XT[(k+3)*XP + r];
        }
        dst4[i4] = o;
    }
}

// ---------------------------------------------------------------------------
extern "C" void kernel_launch(void* const* d_in, const int* in_sizes, int n_in,
                              void* d_out, int out_size)
{
    const float* sub   = (const float*)d_in[0];
    const float* left  = (const float*)d_in[1];
    const float* right = (const float*)d_in[2];

    Params P;
    for (int s = 0; s < 3; ++s) {
        P.W[s]  = (const float*)d_in[3 + 4 * s + 0];
        P.b[s]  = (const float*)d_in[3 + 4 * s + 1];
        P.g[s]  = (const float*)d_in[3 + 4 * s + 2];
        P.be[s] = (const float*)d_in[3 + 4 * s + 3];
    }

    cudaFuncSetAttribute(k_prep, cudaFuncAttributeMaxDynamicSharedMemorySize,
                         PREP_SMEM);
    cudaFuncSetAttribute(k_main, cudaFuncAttributeMaxDynamicSharedMemorySize,
                         SMEM_BYTES);

    k_xtx<<<dim3(P1_BLOCKS, 3), P1_THREADS>>>(sub, left, right);
    k_reduceC<<<(3 * DIN * DIN + 3 * DIN + 255) / 256, 256>>>();
    k_prep<<<3, 256, PREP_SMEM>>>(P, 1.0f / (float)NROWS);
    k_main<<<NROWS / BR, 256, SMEM_BYTES>>>(sub, left, right, (float*)d_out);
}

// round 11
// speedup vs baseline: 1.0259x; 1.0259x over previous
#include <cuda_runtime.h>

// ---------------------------------------------------------------------------
// N=262144 rows, three streams x[N,80]. R_a = BN(x W_a^T + b_a) (batch stats).
// sims = rowwise dots of R pairs -> softmax over 3 -> blend of inputs.
//
// Closed forms:
//   mu_j  = w_j.xbar + b_j
//   var_j = w_j^T (X^T X / N) w_j - (w_j.xbar)^2
//   sim_ab(i) = x_a^T M_ab x_b + u_ab.x_a + v_ab.x_b + c_ab,  M_ab = Wh_a^T Wh_b
//
// R11: zero-MOV ffma2 inner loops. k_xtx lanes = row pairs (transposed tile);
// k_main XT stored q-pair-packed so both ffma2 operands load pre-packed.
// ---------------------------------------------------------------------------

#define DIN    80
#define DOUT   160
#define NROWS  262144
#define EPSV   1e-5f

#define P1_BLOCKS  256        // blocks per stream (pass 1)
#define P1_TILES   8          // 128-row tiles per block: 256*8*128 = 262144
#define P1_THREADS 256
#define P1P 130               // transposed tile pitch (floats)

#define BR 64                 // rows per block (pass 2)
#define P2 66                 // XT2 pitch in float2 units (64 + 2 pad)

// ---- device scratch (static: no runtime allocation allowed) ---------------
__device__ float gSpart[3 * P1_BLOCKS * DIN];            // per-block col sums
__device__ float gS[3 * DIN];                            // column sums
__device__ float gCpart[(size_t)3 * P1_BLOCKS * DIN*DIN];// per-block XtX partials
__device__ float gC[3 * DIN * DIN];                      // XtX per stream
__device__ float gM[3 * DIN * DIN];                      // bilinear matrices
__device__ float gU[3 * DIN];
__device__ float gV[3 * DIN];
__device__ float gCc[3];

struct Params {
    const float* W[3];
    const float* b[3];
    const float* g[3];
    const float* be[3];
};

// packed dual FMA (fma-pipe 2x vs scalar FFMA; PTX-only on sm_10x)
__device__ __forceinline__ float2 ffma2(float2 a, float2 b, float2 c) {
    float2 d;
    asm("fma.rn.f32x2 %0, %1, %2, %3;"
        : "=l"(reinterpret_cast<unsigned long long&>(d))
        : "l"(reinterpret_cast<unsigned long long&>(a)),
          "l"(reinterpret_cast<unsigned long long&>(b)),
          "l"(reinterpret_cast<unsigned long long&>(c)));
    return d;
}

// ---------------------------------------------------------------------------
// K1: per-block partial X^T X (upper block-triangle) + column-sum partials.
// 256 threads = 16(tj) x 16(tk); 5x5 scalar tile, float2 acc lanes = ROW
// PAIRS from the transposed tile XsT[q][r] -> both ffma2 operands are natural
// LDS.64, zero packing MOVs. Lane-sum once at the store.
// ---------------------------------------------------------------------------
__global__ __launch_bounds__(P1_THREADS)
void k_xtx(const float* __restrict__ X0, const float* __restrict__ X1,
           const float* __restrict__ X2)
{
    __shared__ __align__(16) float XsT[DIN * P1P];   // [q][r], 41.6 KB

    const int s = blockIdx.y;
    const float* X = (s == 0) ? X0 : (s == 1) ? X1 : X2;
    const int tid = threadIdx.x;
    const int tj = tid & 15;      // j = tj + 16a
    const int tk = tid >> 4;      // k = tk + 16b

    float2 acc[5][5];
#pragma unroll
    for (int a = 0; a < 5; ++a)
#pragma unroll
        for (int b = 0; b < 5; ++b) acc[a][b] = make_float2(0.f, 0.f);
    float2 cs = make_float2(0.f, 0.f);
    const float2 one2 = make_float2(1.f, 1.f);

    const long long rowbase = (long long)blockIdx.x * (P1_TILES * 128);

    for (int t = 0; t < P1_TILES; ++t) {
        // transpose 128x80 tile into XsT[q][r] (coalesced LDG.128)
        const float4* src4 =
            (const float4*)(X + (rowbase + (long long)t * 128) * DIN);
        for (int i4 = tid; i4 < 128 * DIN / 4; i4 += P1_THREADS) {
            int r  = i4 / 20;
            int k4 = i4 - r * 20;
            float4 v = src4[i4];
            XsT[(4 * k4 + 0) * P1P + r] = v.x;
            XsT[(4 * k4 + 1) * P1P + r] = v.y;
            XsT[(4 * k4 + 2) * P1P + r] = v.z;
            XsT[(4 * k4 + 3) * P1P + r] = v.w;
        }
        __syncthreads();

#pragma unroll 4
        for (int p = 0; p < 64; ++p) {        // 64 row pairs
            float2 xj[5], xk[5];
#pragma unroll
            for (int a = 0; a < 5; ++a)
                xj[a] = *(const float2*)&XsT[(tj + 16 * a) * P1P + 2 * p];
#pragma unroll
            for (int b = 0; b < 5; ++b)
                xk[b] = *(const float2*)&XsT[(tk + 16 * b) * P1P + 2 * p];
#pragma unroll
            for (int a = 0; a < 5; ++a)
#pragma unroll
                for (int b = a; b < 5; ++b)
                    acc[a][b] = ffma2(xj[a], xk[b], acc[a][b]);
        }

        if (tid < DIN) {                      // column sums (contiguous row)
#pragma unroll 8
            for (int p = 0; p < 64; ++p)
                cs = ffma2(*(const float2*)&XsT[tid * P1P + 2 * p], one2, cs);
        }
        __syncthreads();
    }

    float* dst = gCpart + (size_t)(s * P1_BLOCKS + blockIdx.x) * (DIN * DIN);
#pragma unroll
    for (int a = 0; a < 5; ++a)
#pragma unroll
        for (int b = a; b < 5; ++b)
            dst[(tj + 16 * a) * DIN + (tk + 16 * b)] = acc[a][b].x + acc[a][b].y;
    if (tid < DIN)
        gSpart[(s * P1_BLOCKS + blockIdx.x) * DIN + tid] = cs.x + cs.y;
}

// ---------------------------------------------------------------------------
// K2: reduce partials -> gC (mirror lower triangle) and gSpart -> gS.
// ---------------------------------------------------------------------------
__global__ void k_reduceC()
{
    int e = blockIdx.x * blockDim.x + threadIdx.x;
    if (e < 3 * DIN * DIN) {
        int s   = e / (DIN * DIN);
        int rem = e - s * DIN * DIN;
        int j = rem / DIN, k = rem - j * DIN;
        int jt = j >> 4, kt = k >> 4;
        if (jt > kt || (jt == kt && j > k)) return;   // mirror handles these

        const float* src = gCpart + (size_t)s * P1_BLOCKS * (DIN * DIN) + rem;
        float acc = 0.f;
#pragma unroll 8
        for (int b = 0; b < P1_BLOCKS; ++b)
            acc += src[(size_t)b * (DIN * DIN)];
        gC[s * DIN * DIN + j * DIN + k] = acc;
        gC[s * DIN * DIN + k * DIN + j] = acc;
    } else if (e < 3 * DIN * DIN + 3 * DIN) {
        int h = e - 3 * DIN * DIN;
        int s = h / DIN, k = h - s * DIN;
        float acc = 0.f;
#pragma unroll 8
        for (int b = 0; b < P1_BLOCKS; ++b)
            acc += gSpart[(s * P1_BLOCKS + b) * DIN + k];
        gS[s * DIN + k] = acc;
    }
}

// ---------------------------------------------------------------------------
// K3 (fused stats + buildM): grid = 3 blocks (one per pair), 256 threads.
// ---------------------------------------------------------------------------
#define WP 84                                   // W smem pitch
#define TPP (DOUT + 8)                          // Tpart pitch
#define PREP_FLOATS (2*DOUT*WP + DIN*DIN + 16*TPP + DOUT + DIN + 2*DOUT)
#define PREP_SMEM (PREP_FLOATS * 4)

__global__ __launch_bounds__(256)
void k_prep(Params P, float invN)
{
    extern __shared__ __align__(16) float sp[];
    float* WsA    = sp;                         // [160][WP]
    float* WsB    = WsA + DOUT * WP;            // [160][WP]
    float* Cs     = WsB + DOUT * WP;            // [80][80]
    float* Tp     = Cs + DIN * DIN;             // [16][TPP]
    float* alphas = Tp + 16 * TPP;              // [160]
    float* xbs    = alphas + DOUT;              // [80]
    float* dA     = xbs + DIN;                  // [160]
    float* dB     = dA + DOUT;                  // [160]

    const int s = blockIdx.x;
    const int a_idx = (s == 2) ? 1 : 0;         // pa = {0,0,1}
    const int b_idx = (s == 0) ? 1 : 2;         // pb = {1,2,2}
    const int tid = threadIdx.x;
    const int tj = tid & 15, tk = tid >> 4;

    for (int ph = 0; ph < 2; ++ph) {
        const int t  = ph ? b_idx : a_idx;
        float* Ws    = ph ? WsB : WsA;
        float* dd    = ph ? dB : dA;

        const float4* Wg4 = (const float4*)P.W[t];
        for (int i4 = tid; i4 < DOUT * 20; i4 += 256) {
            int j = i4 / 20, k4 = i4 - j * 20;
            *(float4*)&Ws[j * WP + 4 * k4] = Wg4[i4];
        }
        const float4* Cg4 = (const float4*)&gC[t * DIN * DIN];
        float4* Cs4 = (float4*)Cs;
        for (int i4 = tid; i4 < (DIN * DIN) / 4; i4 += 256) Cs4[i4] = Cg4[i4];
        if (tid < DIN) xbs[tid] = gS[t * DIN + tid] * invN;
        __syncthreads();

        float acc[10][5];
#pragma unroll
        for (int aa = 0; aa < 10; ++aa)
#pragma unroll
            for (int bb = 0; bb < 5; ++bb) acc[aa][bb] = 0.f;

        for (int m = 0; m < DIN; ++m) {
            float wv[10], cv[5];
#pragma unroll
            for (int aa = 0; aa < 10; ++aa) wv[aa] = Ws[(tj + 16 * aa) * WP + m];
#pragma unroll
            for (int bb = 0; bb < 5; ++bb)  cv[bb] = Cs[m * DIN + tk + 16 * bb];
#pragma unroll
            for (int aa = 0; aa < 10; ++aa)
#pragma unroll
                for (int bb = 0; bb < 5; ++bb)
                    acc[aa][bb] += wv[aa] * cv[bb];
        }
#pragma unroll
        for (int aa = 0; aa < 10; ++aa) {
            float psum = 0.f;
#pragma unroll
            for (int bb = 0; bb < 5; ++bb)
                psum += acc[aa][bb] * Ws[(tj + 16 * aa) * WP + tk + 16 * bb];
            Tp[tk * TPP + tj + 16 * aa] = psum;
        }
        __syncthreads();

        if (tid < DOUT) {
            float q = 0.f;
#pragma unroll
            for (int g = 0; g < 16; ++g) q += Tp[g * TPP + tid];
            float wx = 0.f;
#pragma unroll 8
            for (int m = 0; m < DIN; ++m) wx += Ws[tid * WP + m] * xbs[m];
            float bj    = P.b[t][tid];
            float mu    = wx + bj;
            float var   = q * invN - wx * wx;
            float alpha = P.g[t][tid] * rsqrtf(var + EPSV);
            dd[tid]     = alpha * bj + (P.be[t][tid] - mu * alpha);
            alphas[tid] = alpha;
        }
        __syncthreads();

        for (int i = tid; i < DOUT * DIN; i += 256) {
            int j = i / DIN, m = i - j * DIN;
            Ws[j * WP + m] *= alphas[j];
        }
        __syncthreads();
    }

    float macc[5][5];
#pragma unroll
    for (int aa = 0; aa < 5; ++aa)
#pragma unroll
        for (int bb = 0; bb < 5; ++bb) macc[aa][bb] = 0.f;

    for (int j = 0; j < DOUT; ++j) {
        float av[5], bv[5];
#pragma unroll
        for (int aa = 0; aa < 5; ++aa) av[aa] = WsA[j * WP + tj + 16 * aa];
#pragma unroll
        for (int bb = 0; bb < 5; ++bb) bv[bb] = WsB[j * WP + tk + 16 * bb];
#pragma unroll
        for (int aa = 0; aa < 5; ++aa)
#pragma unroll
            for (int bb = 0; bb < 5; ++bb)
                macc[aa][bb] += av[aa] * bv[bb];
    }
#pragma unroll
    for (int aa = 0; aa < 5; ++aa)
#pragma unroll
        for (int bb = 0; bb < 5; ++bb)
            gM[s * DIN * DIN + (tj + 16 * aa) * DIN + (tk + 16 * bb)] =
                macc[aa][bb];

    if (tid < DIN) {
        float u = 0.f;
        for (int j = 0; j < DOUT; ++j) u += WsA[j * WP + tid] * dB[j];
        gU[s * DIN + tid] = u;
    } else if (tid < 2 * DIN) {
        int q = tid - DIN;
        float v = 0.f;
        for (int j = 0; j < DOUT; ++j) v += dA[j] * WsB[j * WP + q];
        gV[s * DIN + q] = v;
    } else if (tid == 2 * DIN) {
        float c = 0.f;
        for (int j = 0; j < DOUT; ++j) c += dA[j] * dB[j];
        gCc[s] = c;
    }
}

// ---------------------------------------------------------------------------
// K4: main pass. 64 rows/block, 256 threads = 16(tr: 4 rows) x 16(tc: 5 p).
// XT stored q-pair-packed (float2 lanes = q, q+1): xv = 2x LDS.128 pre-packed,
// mv = natural LDS.64 from row-major M -> zero packing MOVs in the hot loop.
// u folded into the per-row dot phase. psum staging, no atomics.
// ---------------------------------------------------------------------------
#define SM_XT2  0                               // float2 [3][40][P2]
#define SM_M    (3 * 40 * P2 * 2)               // 15840
#define SM_U2   (SM_M + DIN * DIN)              // 22240  (float [3][80])
#define SM_V2   (SM_U2 + 3 * DIN)               // 22480
#define SM_SIM  (SM_V2 + 3 * DIN)               // 22720
#define SM_P    (SM_SIM + 3 * BR)               // 22912
#define SM_CC   (SM_P + 3 * BR)                 // 23104
#define SM_PS   (SM_CC + 8)                     // 23112
#define SM_TOT  (SM_PS + 16 * P2)               // 24168 floats
#define SMEM_BYTES (SM_TOT * 4)                 // 96672 B -> 2 blocks/SM

__global__ __launch_bounds__(256, 2)
void k_main(const float* __restrict__ X0, const float* __restrict__ X1,
            const float* __restrict__ X2, float* __restrict__ out)
{
    extern __shared__ __align__(16) float sm[];
    float2* XT2 = (float2*)(sm + SM_XT2); // [s][qq][r] lanes = (2qq, 2qq+1)
    float* Msm  = sm + SM_M;              // [80][80]
    float* usm  = sm + SM_U2;             // [3][80] (float2-viewable)
    float* vsm  = sm + SM_V2;             // [3][80]
    float* sims = sm + SM_SIM;            // [3][64]
    float* psm  = sm + SM_P;              // [3][64]
    float* ccs  = sm + SM_CC;             // [3]
    float* psum = sm + SM_PS;             // [16][P2]

    const int tid = threadIdx.x;
    const int tr  = tid & 15;     // rows 4*tr .. 4*tr+3
    const int tc  = tid >> 4;     // p = tc + 16*c
    const long long base = (long long)blockIdx.x * BR;

    // ---- phase A: load (float4) + pair-pack x tiles; load u, v, c ---------
    const float* Xp[3] = {X0, X1, X2};
    for (int s = 0; s < 3; ++s) {
        const float4* src4 = (const float4*)(Xp[s] + base * DIN);
        float2* dst = XT2 + s * 40 * P2;
        for (int i4 = tid; i4 < BR * DIN / 4; i4 += 256) {
            int r  = i4 / 20;
            int k4 = i4 - r * 20;
            float4 v = src4[i4];
            dst[(2 * k4 + 0) * P2 + r] = make_float2(v.x, v.y);
            dst[(2 * k4 + 1) * P2 + r] = make_float2(v.z, v.w);
        }
    }
    if (tid < 3 * DIN) { usm[tid] = gU[tid]; vsm[tid] = gV[tid]; }
    if (tid < 3)       ccs[tid] = gCc[tid];
    __syncthreads();

    for (int s = 0; s < 3; ++s) {
        // pa = {0,0,1}, pb = {1,2,2}
        const int a_idx = (s == 2) ? 1 : 0;
        const int b_idx = (s == 0) ? 1 : 2;

        const float4* Mg4 = (const float4*)&gM[s * DIN * DIN];
        float4* Ms4 = (float4*)Msm;
        for (int i = tid; i < (DIN * DIN) / 4; i += 256) Ms4[i] = Mg4[i];
        __syncthreads();

        const float2* Xb = XT2 + b_idx * 40 * P2;

        float2 acc[4][5];
#pragma unroll
        for (int r = 0; r < 4; ++r)
#pragma unroll
            for (int c = 0; c < 5; ++c) acc[r][c] = make_float2(0.f, 0.f);

#pragma unroll 4
        for (int qq = 0; qq < 40; ++qq) {
            float2 xv[4];
            *(float4*)&xv[0] = *(const float4*)&Xb[qq * P2 + 4 * tr];
            *(float4*)&xv[2] = *(const float4*)&Xb[qq * P2 + 4 * tr + 2];
            float2 mv[5];
#pragma unroll
            for (int c = 0; c < 5; ++c)
                mv[c] = *(const float2*)&Msm[(tc + 16 * c) * DIN + 2 * qq];
#pragma unroll
            for (int r = 0; r < 4; ++r)
#pragma unroll
                for (int c = 0; c < 5; ++c)
                    acc[r][c] = ffma2(xv[r], mv[c], acc[r][c]);
        }

        // ---- epilogue: part[r] = sum_c z[p] * x_a[p][4tr+r]  (u moved out)
        const float* XaF = (const float*)(XT2 + a_idx * 40 * P2);
        float part[4] = {0.f, 0.f, 0.f, 0.f};
#pragma unroll
        for (int c = 0; c < 5; ++c) {
            int p = tc + 16 * c;
            const float* ap = XaF + (p >> 1) * (2 * P2) + (p & 1);
#pragma unroll
            for (int r = 0; r < 4; ++r) {
                float z = acc[r][c].x + acc[r][c].y;
                part[r] += z * ap[2 * (4 * tr + r)];
            }
        }
#pragma unroll
        for (int r = 0; r < 4; ++r)
            psum[tc * P2 + 4 * tr + r] = part[r];
        __syncthreads();

        if (tid < BR) {                 // gather across the 16 tc groups
            float v = 0.f;
#pragma unroll
            for (int t = 0; t < 16; ++t) v += psum[t * P2 + tid];
            sims[s * BR + tid] = v;
        }
        __syncthreads();
    }

    // ---- per-row: u,v dots (lane-packed), + c, softmax over 3 sims --------
    if (tid < BR) {
        const int r = tid;
        const float2* x0 = XT2;
        const float2* x1 = XT2 + 40 * P2;
        const float2* x2 = XT2 + 80 * P2;
        const float2* u2 = (const float2*)usm;   // [3][40]
        const float2* v2 = (const float2*)vsm;
        float2 d0 = make_float2(0.f, 0.f), d1 = d0, d2 = d0;
#pragma unroll 8
        for (int qq = 0; qq < 40; ++qq) {
            float2 a  = x0[qq * P2 + r];
            float2 bb = x1[qq * P2 + r];
            float2 cc = x2[qq * P2 + r];
            d0 = ffma2(u2[qq],      a,  d0);
            d0 = ffma2(v2[qq],      bb, d0);
            d1 = ffma2(u2[40 + qq], a,  d1);
            d1 = ffma2(v2[40 + qq], cc, d1);
            d2 = ffma2(u2[80 + qq], bb, d2);
            d2 = ffma2(v2[80 + qq], cc, d2);
        }
        float s0 = sims[0 * BR + r] + d0.x + d0.y + ccs[0];
        float s1 = sims[1 * BR + r] + d1.x + d1.y + ccs[1];
        float s2 = sims[2 * BR + r] + d2.x + d2.y + ccs[2];
        float m  = fmaxf(s0, fmaxf(s1, s2));
        float e0 = __expf(s0 - m), e1 = __expf(s1 - m), e2 = __expf(s2 - m);
        float inv = 1.f / (e0 + e1 + e2);
        psm[0 * BR + r] = e0 * inv;
        psm[1 * BR + r] = e1 * inv;
        psm[2 * BR + r] = e2 * inv;
    }
    __syncthreads();

    // ---- blend + float4 store: out = p0*left + p1*right + p2*sub ----------
    float4* dst4 = (float4*)(out + base * DIN);
    for (int i4 = tid; i4 < BR * DIN / 4; i4 += 256) {
        int r  = i4 / 20;
        int k4 = i4 - r * 20;
        float p0 = psm[r], p1 = psm[BR + r], p2 = psm[2 * BR + r];
        float2 S0 = XT2[(2 * k4) * P2 + r],      S1 = XT2[(2 * k4 + 1) * P2 + r];
        float2 L0 = XT2[(40 + 2 * k4) * P2 + r], L1 = XT2[(40 + 2 * k4 + 1) * P2 + r];
        float2 R0 = XT2[(80 + 2 * k4) * P2 + r], R1 = XT2[(80 + 2 * k4 + 1) * P2 + r];
        float4 o;
        o.x = p0 * L0.x + p1 * R0.x + p2 * S0.x;
        o.y = p0 * L0.y + p1 * R0.y + p2 * S0.y;
        o.z = p0 * L1.x + p1 * R1.x + p2 * S1.x;
        o.w = p0 * L1.y + p1 * R1.y + p2 * S1.y;
        dst4[i4] = o;
    }
}

// ---------------------------------------------------------------------------
extern "C" void kernel_launch(void* const* d_in, const int* in_sizes, int n_in,
                              void* d_out, int out_size)
{
    const float* sub   = (const float*)d_in[0];
    const float* left  = (const float*)d_in[1];
    const float* right = (const float*)d_in[2];

    Params P;
    for (int s = 0; s < 3; ++s) {
        P.W[s]  = (const float*)d_in[3 + 4 * s + 0];
        P.b[s]  = (const float*)d_in[3 + 4 * s + 1];
        P.g[s]  = (const float*)d_in[3 + 4 * s + 2];
        P.be[s] = (const float*)d_in[3 + 4 * s + 3];
    }

    cudaFuncSetAttribute(k_prep, cudaFuncAttributeMaxDynamicSharedMemorySize,
                         PREP_SMEM);
    cudaFuncSetAttribute(k_main, cudaFuncAttributeMaxDynamicSharedMemorySize,
                         SMEM_BYTES);

    k_xtx<<<dim3(P1_BLOCKS, 3), P1_THREADS>>>(sub, left, right);
    k_reduceC<<<(3 * DIN * DIN + 3 * DIN + 255) / 256, 256>>>();
    k_prep<<<3, 256, PREP_SMEM>>>(P, 1.0f / (float)NROWS);
    k_main<<<NROWS / BR, 256, SMEM_BYTES>>>(sub, left, right, (float*)d_out);
}